// round 10
// baseline (speedup 1.0000x reference)
#include <cuda_runtime.h>
#include <cstdint>

#define NB   32
#define NH   64
#define NW   64
#define HO   62
#define WO   62
#define NPB  (HO*WO)            // 3844

// A: [g 12][kw 3][oc 128][slot 8] fp16x2
__device__ __align__(16) uint32_t g_a16[36*1024];            // 147.5 KB

// ---- SMEM geometry (words per buffer) ----
#define AWRD  3072              // 3 kw tiles x 128 oc x 8 slots
#define BROW  72                // B words per c2 row (68 data + 4 pad; 72 % 32 == 8)
#define BWRD  (8*BROW)          // 576
#define STW   (AWRD + BWRD)     // 3648
#define NBUF  3                 // 43776 B static

// ---------------- PTX helpers ----------------
__device__ __forceinline__ uint32_t cvta_s(const void* p) {
    uint32_t a;
    asm("{ .reg .u64 t; cvta.to.shared.u64 t, %1; cvt.u32.u64 %0, t; }" : "=r"(a) : "l"(p));
    return a;
}
__device__ __forceinline__ uint32_t pack_h2(float even, float odd) {
    uint32_t d;
    asm("cvt.rn.f16x2.f32 %0, %1, %2;" : "=r"(d) : "f"(odd), "f"(even));  // lo=even, hi=odd
    return d;
}
__device__ __forceinline__ uint2 lds64(uint32_t addr) {
    uint2 v;
    asm volatile("ld.shared.v2.b32 {%0,%1},[%2];" : "=r"(v.x), "=r"(v.y) : "r"(addr));
    return v;
}
__device__ __forceinline__ uint32_t lds32(uint32_t addr) {
    uint32_t v;
    asm volatile("ld.shared.b32 %0,[%1];" : "=r"(v) : "r"(addr));
    return v;
}
__device__ __forceinline__ void sts128(uint32_t addr, uint4 v) {
    asm volatile("st.shared.v4.b32 [%0],{%1,%2,%3,%4};"
                 :: "r"(addr), "r"(v.x), "r"(v.y), "r"(v.z), "r"(v.w) : "memory");
}
#define CP_A16(dst, src) asm volatile("cp.async.cg.shared.global [%0],[%1],16;" :: "r"(dst), "l"(src))
#define CP_COMMIT()      asm volatile("cp.async.commit_group;" ::: "memory")
#define CP_WAIT0()       asm volatile("cp.async.wait_group 0;" ::: "memory")
#define CP_WAIT1()       asm volatile("cp.async.wait_group 1;" ::: "memory")

__device__ __forceinline__ void mma_f16(float* c, const uint32_t* a, const uint32_t* b) {
    asm volatile(
        "mma.sync.aligned.m16n8k16.row.col.f32.f16.f16.f32 "
        "{%0,%1,%2,%3},{%4,%5,%6,%7},{%8,%9},{%0,%1,%2,%3};"
        : "+f"(c[0]), "+f"(c[1]), "+f"(c[2]), "+f"(c[3])
        : "r"(a[0]), "r"(a[1]), "r"(a[2]), "r"(a[3]), "r"(b[0]), "r"(b[1]));
}

// ---------------- prep kernel (weights only) ----------------
__global__ void prep_w(const float* __restrict__ w) {
    int idx = blockIdx.x * 256 + threadIdx.x;    // 36864
    int slot = idx & 7;
    int oc   = (idx >> 3) & 127;
    int sA   = idx >> 10;          // 0..35 = g*3 + kw
    int g    = sA / 3;
    int kw   = sA - g * 3;
    int kh   = g >> 2;
    int cblk = g & 3;
    int off  = kh * 3 + kw;
    int p    = (slot >> 1) + 4 * (slot & 1);
    int ce   = cblk * 16 + 2 * p;
    g_a16[idx] = pack_h2(w[oc * 576 + ce * 9 + off], w[oc * 576 + (ce + 1) * 9 + off]);
}

// ---------------- main kernel ----------------
// CTA: 128 oc x 64 wo, ONE output row. 8 warps = 4 oc-quarters x 2 wo-halves.
__global__ __launch_bounds__(256, 3) void conv_main(const float* __restrict__ x,
                                                    float* __restrict__ out) {
    __shared__ __align__(16) uint32_t sm[NBUF * STW];    // 43776 B

    const int tid  = threadIdx.x;
    const int lane = tid & 31;
    const int warp = tid >> 5;
    const int wq   = warp >> 1;        // 0..3 : oc quarter
    const int wh   = warp & 1;         // 0..1 : wo half
    const int cW   = wh * 32;

    const int b  = blockIdx.y;
    const int ho = blockIdx.x;         // 0..61

    const uint32_t smem_b = cvta_s(sm);

    // ---- B staging descriptors: 136 groups (c2 8 x q 17) ----
    const bool hasB = (tid < 136);
    const float* bsrc0 = x;
    uint32_t bdst0 = 0;
    if (hasB) {
        int run = tid / 17, q = tid - run * 17;
        int qe = (q > 15) ? 15 : q;    // clamp source; slots 64..67 garbage, never consumed
        bsrc0 = x + ((size_t)(b * 64 + 2 * run)) * 4096 + ho * 64 + 4 * qe;
        bdst0 = (uint32_t)(AWRD + run * BROW + 4 * q);
    }

    float acc[2][4][4];
    #pragma unroll
    for (int mi = 0; mi < 2; ++mi)
        #pragma unroll
        for (int ni = 0; ni < 4; ++ni)
            #pragma unroll
            for (int q = 0; q < 4; ++q) acc[mi][ni][q] = 0.0f;

    const uint32_t a_fw = ((uint32_t)(wq * 32 + (lane >> 2)) * 8 + (lane & 3) * 2) * 4;
    const uint32_t b_fw = (uint32_t)(AWRD + (lane & 3) * BROW + cW + (lane >> 2)) * 4;

    auto issueA = [&](int g, uint32_t bufw) {
        const uint4* asrc = (const uint4*)(g_a16 + g * AWRD) + tid;
        const uint32_t adst = smem_b + bufw * 4 + (uint32_t)tid * 16;
        CP_A16(adst,        asrc);
        CP_A16(adst + 4096, asrc + 256);
        CP_A16(adst + 8192, asrc + 512);
        CP_COMMIT();
    };
    auto bSoff = [](int g) -> uint32_t {
        return (uint32_t)((g & 3) * 16 * 4096 + (g >> 2) * 64);   // floats
    };

    // ---- prologue ----
    issueA(0, 0);
    issueA(1, STW);
    if (hasB) {
        const uint32_t so = bSoff(0);
        float4 e0 = *(const float4*)(bsrc0 + so);
        float4 o0 = *(const float4*)(bsrc0 + so + 4096);
        uint4 v0;
        v0.x = pack_h2(e0.x, o0.x); v0.y = pack_h2(e0.y, o0.y);
        v0.z = pack_h2(e0.z, o0.z); v0.w = pack_h2(e0.w, o0.w);
        sts128(smem_b + bdst0 * 4, v0);
    }

    uint32_t cbuf = 0;

    #pragma unroll 1
    for (int s = 0; s < 12; ++s) {
        if (s < 11) { CP_WAIT1(); } else { CP_WAIT0(); }
        __syncthreads();

        if (s + 2 < 12) {
            uint32_t b2 = cbuf + 2 * STW; if (b2 >= NBUF * STW) b2 -= NBUF * STW;
            issueA(s + 2, b2);
        }

        // B loads for next stage
        float4 e0, o0;
        const bool haveNext = (s + 1 < 12);
        if (haveNext && hasB) {
            const uint32_t so = bSoff(s + 1);
            e0 = *(const float4*)(bsrc0 + so);
            o0 = *(const float4*)(bsrc0 + so + 4096);
        }

        // ---- compute stage s ----
        const uint32_t abase0 = smem_b + cbuf * 4 + a_fw;
        const uint32_t bbase0 = smem_b + cbuf * 4 + b_fw;

        #pragma unroll
        for (int kw = 0; kw < 3; ++kw) {
            const uint32_t abase = abase0 + (uint32_t)kw * 4096;
            const uint32_t bbase = bbase0 + (uint32_t)kw * 4;

            uint32_t af[2][4], bf[4][2];
            #pragma unroll
            for (int mi = 0; mi < 2; ++mi) {
                uint2 t0 = lds64(abase + (uint32_t)mi * 512);
                uint2 t1 = lds64(abase + (uint32_t)(mi * 512 + 256));
                af[mi][0] = t0.x; af[mi][1] = t1.x; af[mi][2] = t0.y; af[mi][3] = t1.y;
            }
            #pragma unroll
            for (int ni = 0; ni < 4; ++ni) {
                bf[ni][0] = lds32(bbase + (uint32_t)ni * 32);
                bf[ni][1] = lds32(bbase + (uint32_t)ni * 32 + 4 * BROW * 4);
            }
            #pragma unroll
            for (int mi = 0; mi < 2; ++mi)
                #pragma unroll
                for (int ni = 0; ni < 4; ++ni)
                    mma_f16(acc[mi][ni], af[mi], bf[ni]);
        }

        // ---- pack + store B(s+1) ----
        if (haveNext && hasB) {
            uint32_t nbuf = cbuf + STW; if (nbuf >= NBUF * STW) nbuf -= NBUF * STW;
            uint4 v0;
            v0.x = pack_h2(e0.x, o0.x); v0.y = pack_h2(e0.y, o0.y);
            v0.z = pack_h2(e0.z, o0.z); v0.w = pack_h2(e0.w, o0.w);
            sts128(smem_b + (nbuf + bdst0) * 4, v0);
        }

        cbuf += STW; if (cbuf == NBUF * STW) cbuf = 0;
    }

    // ---- epilogue ----
    #pragma unroll
    for (int mi = 0; mi < 2; ++mi) {
        #pragma unroll
        for (int ni = 0; ni < 4; ++ni) {
            const int ocr = wq * 32 + mi * 16 + (lane >> 2);
            const int wo  = cW + ni * 8 + 2 * (lane & 3);
            if (wo < WO) {
                const size_t base = (size_t)ho * WO + wo;
                float* p0 = out + ((size_t)ocr * NB + b) * NPB + base;
                *(float2*)p0 = make_float2(acc[mi][ni][0], acc[mi][ni][1]);
                float* p1 = out + ((size_t)(ocr + 8) * NB + b) * NPB + base;
                *(float2*)p1 = make_float2(acc[mi][ni][2], acc[mi][ni][3]);
            }
        }
    }
}

// ---------------- launch ----------------
extern "C" void kernel_launch(void* const* d_in, const int* in_sizes, int n_in,
                              void* d_out, int out_size) {
    const float* x = (const float*)d_in[0];
    const float* w = (const float*)d_in[1];
    float* out = (float*)d_out;

    prep_w<<<144, 256>>>(w);
    conv_main<<<dim3(HO, NB), 256>>>(x, out);
}